// round 4
// baseline (speedup 1.0000x reference)
#include <cuda_runtime.h>
#include <stdint.h>

// EGCN: x0 = l2norm(emb); x1 = scatter_add(x0[src]*w -> dst); x2 = scatter_add(x1[src]*w -> dst);
// out = x0 + x1 + x2.
// N=100000 nodes, DIM=64, E=1.6M edges, 2 layers.
// adj arrives as int32 (harness canonicalizes int64 -> int32).

constexpr int N_NODES = 100000;
constexpr int DIM     = 64;
constexpr int DIM4    = DIM / 4;   // 16 float4 per row

// Scratch (static device globals; allocation-free contract). float4 => 16B aligned.
__device__ float4 g_x0[(long long)N_NODES * DIM4];
__device__ float4 g_x1[(long long)N_NODES * DIM4];
__device__ float4 g_x2[(long long)N_NODES * DIM4];

// ---------------------------------------------------------------------------
// Kernel 1: L2-normalize rows of emb into g_x0, and zero g_x1/g_x2.
// One warp per row; lane covers elements [lane] and [lane+32].
// ---------------------------------------------------------------------------
__global__ __launch_bounds__(256) void normalize_zero_kernel(const float* __restrict__ emb) {
    int warp = (blockIdx.x * blockDim.x + threadIdx.x) >> 5;
    int lane = threadIdx.x & 31;
    if (warp >= N_NODES) return;

    long long base = (long long)warp * DIM;
    float a = emb[base + lane];
    float b = emb[base + lane + 32];
    float ss = a * a + b * b;
    #pragma unroll
    for (int o = 16; o; o >>= 1) ss += __shfl_xor_sync(0xffffffffu, ss, o);
    float inv = 1.0f / fmaxf(sqrtf(ss), 1e-12f);

    float* x0 = reinterpret_cast<float*>(g_x0);
    float* x1 = reinterpret_cast<float*>(g_x1);
    float* x2 = reinterpret_cast<float*>(g_x2);

    x0[base + lane]      = a * inv;
    x0[base + lane + 32] = b * inv;
    x1[base + lane]      = 0.0f;
    x1[base + lane + 32] = 0.0f;
    x2[base + lane]      = 0.0f;
    x2[base + lane + 32] = 0.0f;
}

// ---------------------------------------------------------------------------
// Vector f32 reduction into global memory (sm_90+). Target must be 16B aligned.
// ---------------------------------------------------------------------------
__device__ __forceinline__ void red_add_v4(float4* addr, float x, float y, float z, float w) {
    asm volatile("red.global.add.v4.f32 [%0], {%1, %2, %3, %4};"
                 :: "l"(addr), "f"(x), "f"(y), "f"(z), "f"(w)
                 : "memory");
}

// ---------------------------------------------------------------------------
// Kernel 2/3: one GCN layer. 16 threads per edge; each handles one float4
// (16 B) of the 256 B row. xout[dst] += xin[src] * w.
// ---------------------------------------------------------------------------
__global__ __launch_bounds__(256) void edge_layer_kernel(
    const float4* __restrict__ xin,      // [N_NODES * DIM4]
    float4*       __restrict__ xout,     // [N_NODES * DIM4]
    const int*    __restrict__ adj,      // [2, num_edges] int32
    const float*  __restrict__ wvec,     // [num_edges]
    int num_edges)
{
    long long tid = (long long)blockIdx.x * blockDim.x + threadIdx.x;
    long long e   = tid >> 4;            // edge index
    int       c   = (int)(tid & 15);     // float4 chunk within row
    if (e >= num_edges) return;

    int   src = adj[e];
    int   dst = adj[(long long)num_edges + e];
    float w   = wvec[e];

    float4 v = xin[(long long)src * DIM4 + c];
    red_add_v4(xout + (long long)dst * DIM4 + c, v.x * w, v.y * w, v.z * w, v.w * w);
}

// ---------------------------------------------------------------------------
// Kernel 4: out = x0 + x1 + x2 (float4 elementwise)
// ---------------------------------------------------------------------------
__global__ __launch_bounds__(256) void final_sum_kernel(float4* __restrict__ out) {
    long long i = (long long)blockIdx.x * blockDim.x + threadIdx.x;
    constexpr long long TOTAL4 = (long long)N_NODES * DIM4;
    if (i >= TOTAL4) return;
    float4 a = g_x0[i], b = g_x1[i], c = g_x2[i];
    float4 r;
    r.x = a.x + b.x + c.x;
    r.y = a.y + b.y + c.y;
    r.z = a.z + b.z + c.z;
    r.w = a.w + b.w + c.w;
    out[i] = r;
}

// ---------------------------------------------------------------------------
// kernel_launch
// ---------------------------------------------------------------------------
extern "C" void kernel_launch(void* const* d_in, const int* in_sizes, int n_in,
                              void* d_out, int out_size) {
    const float* emb = (const float*)d_in[0];  // [100000, 64] f32
    const float* wv  = (const float*)d_in[1];  // [1600000, 1] f32
    const int*   adj = (const int*)d_in[2];    // [2, 1600000] int32

    int num_edges = in_sizes[1];               // weight_vector element count = E

    float4* x0;
    float4* x1;
    float4* x2;
    cudaGetSymbolAddress((void**)&x0, g_x0);
    cudaGetSymbolAddress((void**)&x1, g_x1);
    cudaGetSymbolAddress((void**)&x2, g_x2);

    // 1) normalize + zero scratch: one warp per node
    {
        int threads = 256;
        int blocks  = (N_NODES * 32 + threads - 1) / threads;
        normalize_zero_kernel<<<blocks, threads>>>(emb);
    }

    // 2) layer 1: x0 -> x1
    {
        long long total = (long long)num_edges * 16;
        int threads = 256;
        int blocks  = (int)((total + threads - 1) / threads);
        edge_layer_kernel<<<blocks, threads>>>(x0, x1, adj, wv, num_edges);
    }

    // 3) layer 2: x1 -> x2
    {
        long long total = (long long)num_edges * 16;
        int threads = 256;
        int blocks  = (int)((total + threads - 1) / threads);
        edge_layer_kernel<<<blocks, threads>>>(x1, x2, adj, wv, num_edges);
    }

    // 4) out = x0 + x1 + x2
    {
        long long total4 = (long long)N_NODES * DIM4;
        int threads = 256;
        int blocks  = (int)((total4 + threads - 1) / threads);
        final_sum_kernel<<<blocks, threads>>>(reinterpret_cast<float4*>(d_out));
    }
}

// round 5
// speedup vs baseline: 1.0600x; 1.0600x over previous
#include <cuda_runtime.h>
#include <stdint.h>

// EGCN: x0 = l2norm(emb); x1 = scatter(x0[src]*w -> dst); out = x0+x1 + scatter(x1[src]*w -> dst).
// N=100000 nodes, DIM=64, E=1.6M edges. adj arrives as int32.

constexpr int N_NODES = 100000;
constexpr int DIM     = 64;
constexpr int DIM4    = DIM / 4;   // 16 float4 per row

// Scratch (static device globals; allocation-free contract). float4 => 16B aligned.
__device__ float4 g_x0[(long long)N_NODES * DIM4];
__device__ float4 g_x1[(long long)N_NODES * DIM4];

// ---------------------------------------------------------------------------
// Kernel 1: L2-normalize rows of emb into g_x0 (float4), zero g_x1.
// 16-lane group per row (2 rows per warp); each lane owns one float4.
// ---------------------------------------------------------------------------
__global__ __launch_bounds__(256) void normalize_zero_kernel(const float4* __restrict__ emb) {
    int tid  = blockIdx.x * blockDim.x + threadIdx.x;
    int row  = tid >> 4;
    int lane = tid & 15;
    if (row >= N_NODES) return;

    long long idx = (long long)row * DIM4 + lane;
    float4 v = emb[idx];
    float ss = v.x * v.x + v.y * v.y + v.z * v.z + v.w * v.w;
    #pragma unroll
    for (int o = 8; o; o >>= 1) ss += __shfl_xor_sync(0xffffffffu, ss, o, 16);
    float inv = 1.0f / fmaxf(sqrtf(ss), 1e-12f);

    float4 r;
    r.x = v.x * inv; r.y = v.y * inv; r.z = v.z * inv; r.w = v.w * inv;
    g_x0[idx] = r;
    g_x1[idx] = make_float4(0.f, 0.f, 0.f, 0.f);
}

// ---------------------------------------------------------------------------
// Vector f32 reduction into global memory (sm_90+). Target must be 16B aligned.
// ---------------------------------------------------------------------------
__device__ __forceinline__ void red_add_v4(float4* addr, float x, float y, float z, float w) {
    asm volatile("red.global.add.v4.f32 [%0], {%1, %2, %3, %4};"
                 :: "l"(addr), "f"(x), "f"(y), "f"(z), "f"(w)
                 : "memory");
}

// ---------------------------------------------------------------------------
// Kernel 2/4: one GCN layer. 4 threads per edge; each thread handles 4 float4
// chunks (loads batched first for MLP, then 4 v4 reds).
// xout[dst] += xin[src] * w.
// ---------------------------------------------------------------------------
__global__ __launch_bounds__(256) void edge_layer_kernel(
    const float4* __restrict__ xin,      // [N_NODES * DIM4]
    float4*       __restrict__ xout,     // [N_NODES * DIM4]
    const int*    __restrict__ adj,      // [2, num_edges] int32
    const float*  __restrict__ wvec,     // [num_edges]
    int num_edges)
{
    int tid = blockIdx.x * blockDim.x + threadIdx.x;   // num_edges*4 <= 6.4M, fits int
    int e   = tid >> 2;
    int c   = tid & 3;
    if (e >= num_edges) return;

    int   src = adj[e];
    int   dst = adj[num_edges + e];
    float w   = wvec[e];

    const float4* srow = xin  + (long long)src * DIM4;
    float4*       drow = xout + (long long)dst * DIM4;

    // Batch the 4 independent gathers first (MLP=4), then the 4 reductions.
    float4 v0 = srow[c + 0];
    float4 v1 = srow[c + 4];
    float4 v2 = srow[c + 8];
    float4 v3 = srow[c + 12];

    red_add_v4(drow + c + 0,  v0.x * w, v0.y * w, v0.z * w, v0.w * w);
    red_add_v4(drow + c + 4,  v1.x * w, v1.y * w, v1.z * w, v1.w * w);
    red_add_v4(drow + c + 8,  v2.x * w, v2.y * w, v2.z * w, v2.w * w);
    red_add_v4(drow + c + 12, v3.x * w, v3.y * w, v3.z * w, v3.w * w);
}

// ---------------------------------------------------------------------------
// Kernel 3: prefill out = x0 + x1 (layer-2 reds then accumulate into out).
// ---------------------------------------------------------------------------
__global__ __launch_bounds__(256) void prefill_kernel(float4* __restrict__ out) {
    long long i = (long long)blockIdx.x * blockDim.x + threadIdx.x;
    constexpr long long TOTAL4 = (long long)N_NODES * DIM4;
    if (i >= TOTAL4) return;
    float4 a = g_x0[i], b = g_x1[i];
    float4 r;
    r.x = a.x + b.x;
    r.y = a.y + b.y;
    r.z = a.z + b.z;
    r.w = a.w + b.w;
    out[i] = r;
}

// ---------------------------------------------------------------------------
// kernel_launch
// ---------------------------------------------------------------------------
extern "C" void kernel_launch(void* const* d_in, const int* in_sizes, int n_in,
                              void* d_out, int out_size) {
    const float4* emb = (const float4*)d_in[0]; // [100000, 64] f32 (16B-aligned rows)
    const float*  wv  = (const float*)d_in[1];  // [1600000, 1] f32
    const int*    adj = (const int*)d_in[2];    // [2, 1600000] int32

    int num_edges = in_sizes[1];                // weight_vector element count = E

    float4* x0;
    float4* x1;
    cudaGetSymbolAddress((void**)&x0, g_x0);
    cudaGetSymbolAddress((void**)&x1, g_x1);

    float4* out4 = reinterpret_cast<float4*>(d_out);

    const int threads = 256;

    // 1) normalize + zero x1: 16 threads per node
    {
        long long total = (long long)N_NODES * 16;
        int blocks = (int)((total + threads - 1) / threads);
        normalize_zero_kernel<<<blocks, threads>>>(emb);
    }

    // 2) layer 1: x0 -> x1 (4 threads per edge)
    {
        long long total = (long long)num_edges * 4;
        int blocks = (int)((total + threads - 1) / threads);
        edge_layer_kernel<<<blocks, threads>>>(x0, x1, adj, wv, num_edges);
    }

    // 3) prefill out = x0 + x1
    {
        long long total4 = (long long)N_NODES * DIM4;
        int blocks = (int)((total4 + threads - 1) / threads);
        prefill_kernel<<<blocks, threads>>>(out4);
    }

    // 4) layer 2: x1 -> out (reds accumulate on top of x0 + x1)
    {
        long long total = (long long)num_edges * 4;
        int blocks = (int)((total + threads - 1) / threads);
        edge_layer_kernel<<<blocks, threads>>>(x1, out4, adj, wv, num_edges);
    }
}

// round 6
// speedup vs baseline: 1.2572x; 1.1860x over previous
#include <cuda_runtime.h>
#include <stdint.h>

// EGCN: x0 = l2norm(emb); x1 = scatter(x0[src]*w -> dst); out = x0+x1 + scatter(x1[src]*w -> dst).
// N=100000 nodes, DIM=64, E=1.6M edges. adj arrives as int32.

constexpr int N_NODES = 100000;
constexpr int DIM     = 64;
constexpr int DIM4    = DIM / 4;   // 16 float4 per row

// Scratch (static device globals; allocation-free contract). float4 => 16B aligned;
// rows are 256B so each row spans exactly two 128B lines.
__device__ float4 g_x0[(long long)N_NODES * DIM4];
__device__ float4 g_x1[(long long)N_NODES * DIM4];

// ---------------------------------------------------------------------------
// Kernel 1: L2-normalize rows of emb into g_x0 (float4), zero g_x1.
// 16-lane group per row (2 rows per warp); each lane owns one float4.
// ---------------------------------------------------------------------------
__global__ __launch_bounds__(256) void normalize_zero_kernel(const float4* __restrict__ emb) {
    int tid  = blockIdx.x * blockDim.x + threadIdx.x;
    int row  = tid >> 4;
    int lane = tid & 15;
    if (row >= N_NODES) return;

    long long idx = (long long)row * DIM4 + lane;
    float4 v = emb[idx];
    float ss = v.x * v.x + v.y * v.y + v.z * v.z + v.w * v.w;
    #pragma unroll
    for (int o = 8; o; o >>= 1) ss += __shfl_xor_sync(0xffffffffu, ss, o, 16);
    float inv = 1.0f / fmaxf(sqrtf(ss), 1e-12f);

    float4 r;
    r.x = v.x * inv; r.y = v.y * inv; r.z = v.z * inv; r.w = v.w * inv;
    g_x0[idx] = r;
    g_x1[idx] = make_float4(0.f, 0.f, 0.f, 0.f);
}

// ---------------------------------------------------------------------------
// Vector f32 reduction into global memory (sm_90+). Target must be 16B aligned.
// ---------------------------------------------------------------------------
__device__ __forceinline__ void red_add_v4(float4* addr, float x, float y, float z, float w) {
    asm volatile("red.global.add.v4.f32 [%0], {%1, %2, %3, %4};"
                 :: "l"(addr), "f"(x), "f"(y), "f"(z), "f"(w)
                 : "memory");
}

// ---------------------------------------------------------------------------
// Kernel 2/4: one GCN layer. 8 threads per edge; thread handles chunks c and
// c+8, so lanes 0..7 of an edge cover exactly one 128B line and lanes with
// c+8 the second line. Every warp-level LDG.128 / RED.128 touches 4 rows x
// one full 128B line = minimal L1 wavefront count.
// xout[dst] += xin[src] * w.
// ---------------------------------------------------------------------------
__global__ __launch_bounds__(256) void edge_layer_kernel(
    const float4* __restrict__ xin,      // [N_NODES * DIM4]
    float4*       __restrict__ xout,     // [N_NODES * DIM4]
    const int*    __restrict__ adj,      // [2, num_edges] int32
    const float*  __restrict__ wvec,     // [num_edges]
    int num_edges)
{
    int tid = blockIdx.x * blockDim.x + threadIdx.x;   // num_edges*8 <= 12.8M, fits int
    int e   = tid >> 3;
    int c   = tid & 7;
    if (e >= num_edges) return;

    int   src = adj[e];
    int   dst = adj[num_edges + e];
    float w   = wvec[e];

    const float4* srow = xin  + (long long)src * DIM4;
    float4*       drow = xout + (long long)dst * DIM4;

    // Batch the 2 independent line gathers first (MLP=2), then the reductions.
    float4 v0 = srow[c];
    float4 v1 = srow[c + 8];

    red_add_v4(drow + c,     v0.x * w, v0.y * w, v0.z * w, v0.w * w);
    red_add_v4(drow + c + 8, v1.x * w, v1.y * w, v1.z * w, v1.w * w);
}

// ---------------------------------------------------------------------------
// Kernel 3: prefill out = x0 + x1 (layer-2 reds then accumulate into out).
// ---------------------------------------------------------------------------
__global__ __launch_bounds__(256) void prefill_kernel(float4* __restrict__ out) {
    long long i = (long long)blockIdx.x * blockDim.x + threadIdx.x;
    constexpr long long TOTAL4 = (long long)N_NODES * DIM4;
    if (i >= TOTAL4) return;
    float4 a = g_x0[i], b = g_x1[i];
    float4 r;
    r.x = a.x + b.x;
    r.y = a.y + b.y;
    r.z = a.z + b.z;
    r.w = a.w + b.w;
    out[i] = r;
}

// ---------------------------------------------------------------------------
// kernel_launch
// ---------------------------------------------------------------------------
extern "C" void kernel_launch(void* const* d_in, const int* in_sizes, int n_in,
                              void* d_out, int out_size) {
    const float4* emb = (const float4*)d_in[0]; // [100000, 64] f32 (16B-aligned rows)
    const float*  wv  = (const float*)d_in[1];  // [1600000, 1] f32
    const int*    adj = (const int*)d_in[2];    // [2, 1600000] int32

    int num_edges = in_sizes[1];                // weight_vector element count = E

    float4* x0;
    float4* x1;
    cudaGetSymbolAddress((void**)&x0, g_x0);
    cudaGetSymbolAddress((void**)&x1, g_x1);

    float4* out4 = reinterpret_cast<float4*>(d_out);

    const int threads = 256;

    // 1) normalize + zero x1: 16 threads per node
    {
        long long total = (long long)N_NODES * 16;
        int blocks = (int)((total + threads - 1) / threads);
        normalize_zero_kernel<<<blocks, threads>>>(emb);
    }

    // 2) layer 1: x0 -> x1 (8 threads per edge)
    {
        long long total = (long long)num_edges * 8;
        int blocks = (int)((total + threads - 1) / threads);
        edge_layer_kernel<<<blocks, threads>>>(x0, x1, adj, wv, num_edges);
    }

    // 3) prefill out = x0 + x1
    {
        long long total4 = (long long)N_NODES * DIM4;
        int blocks = (int)((total4 + threads - 1) / threads);
        prefill_kernel<<<blocks, threads>>>(out4);
    }

    // 4) layer 2: x1 -> out (reds accumulate on top of x0 + x1)
    {
        long long total = (long long)num_edges * 8;
        int blocks = (int)((total + threads - 1) / threads);
        edge_layer_kernel<<<blocks, threads>>>(x1, out4, adj, wv, num_edges);
    }
}

// round 9
// speedup vs baseline: 1.6866x; 1.3415x over previous
#include <cuda_runtime.h>
#include <stdint.h>

// EGCN pull-mode: build CSR-by-dst on device, then per-node register aggregation.
// x0 = l2norm(emb); x1 = A x0; out = x0 + x1 + A x1   (A = weighted adjacency)
// N=100000, DIM=64, E=1.6M. adj arrives int32.

constexpr int N_NODES = 100000;
constexpr int DIM     = 64;
constexpr int DIM4    = DIM / 4;     // 16 float4 per row
constexpr int MAX_E   = 1600000;
constexpr int SCAN_B  = 512;                                  // elems per scan block
constexpr int NUM_SB  = (N_NODES + SCAN_B - 1) / SCAN_B;      // 196 scan blocks

// ---- device scratch (allocation-free contract) ----
__device__ float4 g_x0[(long long)N_NODES * DIM4];
__device__ float4 g_x1[(long long)N_NODES * DIM4];
__device__ int    g_cnt[N_NODES];        // in-degree histogram
__device__ int    g_off[N_NODES + 1];    // exclusive offsets
__device__ int    g_cur[N_NODES];        // scatter cursors
__device__ int    g_bsum[256];           // scan block sums
__device__ int2   g_edge[MAX_E];         // {src, w_bits} sorted by dst

// ---------------------------------------------------------------------------
// 1) normalize rows into g_x0; also zero histogram counters.
// (N_NODES*16 threads; divides 256 exactly -> no intra-warp early exit.)
// ---------------------------------------------------------------------------
__global__ __launch_bounds__(256) void normalize_kernel(const float4* __restrict__ emb) {
    int tid  = blockIdx.x * blockDim.x + threadIdx.x;
    int row  = tid >> 4;
    int lane = tid & 15;
    if (row < N_NODES && lane == 0) g_cnt[row] = 0;
    if (row >= N_NODES) return;

    long long idx = (long long)row * DIM4 + lane;
    float4 v = emb[idx];
    float ss = v.x * v.x + v.y * v.y + v.z * v.z + v.w * v.w;
    #pragma unroll
    for (int o = 8; o; o >>= 1) ss += __shfl_xor_sync(0xffffffffu, ss, o, 16);
    float inv = 1.0f / fmaxf(sqrtf(ss), 1e-12f);
    g_x0[idx] = make_float4(v.x * inv, v.y * inv, v.z * inv, v.w * inv);
}

// ---------------------------------------------------------------------------
// 2) histogram of dst
// ---------------------------------------------------------------------------
__global__ __launch_bounds__(256) void hist_kernel(const int* __restrict__ adj, int num_edges) {
    int e = blockIdx.x * blockDim.x + threadIdx.x;
    if (e >= num_edges) return;
    atomicAdd(&g_cnt[adj[num_edges + e]], 1);
}

// ---------------------------------------------------------------------------
// 3a) per-block exclusive scan of g_cnt -> g_off, block totals -> g_bsum
// ---------------------------------------------------------------------------
__global__ __launch_bounds__(SCAN_B) void scan_block_kernel() {
    __shared__ int warp_sums[SCAN_B / 32];   // 16
    int t    = threadIdx.x;
    int gid  = blockIdx.x * SCAN_B + t;
    int lane = t & 31, wid = t >> 5;

    int v = (gid < N_NODES) ? g_cnt[gid] : 0;
    int x = v;
    #pragma unroll
    for (int o = 1; o < 32; o <<= 1) {
        int y = __shfl_up_sync(0xffffffffu, x, o);
        if (lane >= o) x += y;
    }
    if (lane == 31) warp_sums[wid] = x;
    __syncthreads();
    // Second-level scan: ALL 32 lanes of warp 0 execute the shuffles
    // (lanes >= 16 carry 0); only lanes < 16 store. Full-mask-safe.
    if (wid == 0) {
        int s = (lane < SCAN_B / 32) ? warp_sums[lane] : 0;
        #pragma unroll
        for (int o = 1; o < SCAN_B / 32; o <<= 1) {
            int y = __shfl_up_sync(0xffffffffu, s, o);
            if (lane >= o) s += y;
        }
        if (lane < SCAN_B / 32) warp_sums[lane] = s;
    }
    __syncthreads();
    int prefix = (wid > 0) ? warp_sums[wid - 1] : 0;
    int incl   = prefix + x;
    if (gid < N_NODES) g_off[gid] = incl - v;
    if (t == SCAN_B - 1) g_bsum[blockIdx.x] = incl;
}

// ---------------------------------------------------------------------------
// 3b) scan the block sums (single block, Hillis-Steele in shared; uniform CF)
// ---------------------------------------------------------------------------
__global__ __launch_bounds__(256) void scan_sums_kernel() {
    __shared__ int sh[256];
    int t = threadIdx.x;
    int v = (t < NUM_SB) ? g_bsum[t] : 0;
    sh[t] = v;
    __syncthreads();
    #pragma unroll
    for (int o = 1; o < 256; o <<= 1) {
        int y = (t >= o) ? sh[t - o] : 0;
        __syncthreads();
        sh[t] += y;
        __syncthreads();
    }
    g_bsum[t] = sh[t] - v;   // exclusive
}

// ---------------------------------------------------------------------------
// 3c) add block offsets; init cursors; set g_off[N]
// ---------------------------------------------------------------------------
__global__ __launch_bounds__(256) void scan_fixup_kernel(int num_edges) {
    int i = blockIdx.x * blockDim.x + threadIdx.x;
    if (i >= N_NODES) return;
    int o = g_off[i] + g_bsum[i / SCAN_B];
    g_off[i] = o;
    g_cur[i] = o;
    if (i == 0) g_off[N_NODES] = num_edges;
}

// ---------------------------------------------------------------------------
// 4) scatter edges into dst-sorted order: g_edge[pos] = {src, w}
// ---------------------------------------------------------------------------
__global__ __launch_bounds__(256) void scatter_kernel(
    const int* __restrict__ adj, const float* __restrict__ wvec, int num_edges) {
    int e = blockIdx.x * blockDim.x + threadIdx.x;
    if (e >= num_edges) return;
    int dst = adj[num_edges + e];
    int pos = atomicAdd(&g_cur[dst], 1);
    g_edge[pos] = make_int2(adj[e], __float_as_int(wvec[e]));
}

// ---------------------------------------------------------------------------
// 5) pull layer: one warp per node. Lanes split into two 16-lane halves,
// each half processes alternating in-edges; lane c owns float4 chunk c.
// out[node] = (base0+base1 if given) + sum_e x[src_e]*w_e.
// (N_NODES*32 threads; divides 256 exactly -> whole warps exit together.)
// ---------------------------------------------------------------------------
__global__ __launch_bounds__(256) void pull_layer_kernel(
    const float4* __restrict__ xin,
    float4*       __restrict__ xout,
    const float4* __restrict__ base0,   // nullable
    const float4* __restrict__ base1)   // nullable
{
    int warp = (blockIdx.x * blockDim.x + threadIdx.x) >> 5;
    if (warp >= N_NODES) return;
    int lane = threadIdx.x & 31;
    int half = lane >> 4;       // 0 or 1
    int c    = lane & 15;       // chunk

    int beg = g_off[warp];
    int end = g_off[warp + 1];

    float4 acc = make_float4(0.f, 0.f, 0.f, 0.f);
    for (int p = beg + half; p < end; p += 2) {
        int2  ew = g_edge[p];
        float w  = __int_as_float(ew.y);
        float4 v = xin[(long long)ew.x * DIM4 + c];
        acc.x += v.x * w; acc.y += v.y * w; acc.z += v.z * w; acc.w += v.w * w;
    }
    // combine the two halves (lane c += lane c+16); all 32 lanes reach here.
    acc.x += __shfl_xor_sync(0xffffffffu, acc.x, 16);
    acc.y += __shfl_xor_sync(0xffffffffu, acc.y, 16);
    acc.z += __shfl_xor_sync(0xffffffffu, acc.z, 16);
    acc.w += __shfl_xor_sync(0xffffffffu, acc.w, 16);

    if (half == 0) {
        long long idx = (long long)warp * DIM4 + c;
        if (base0) {
            float4 b0 = base0[idx], b1 = base1[idx];
            acc.x += b0.x + b1.x; acc.y += b0.y + b1.y;
            acc.z += b0.z + b1.z; acc.w += b0.w + b1.w;
        }
        xout[idx] = acc;
    }
}

// ---------------------------------------------------------------------------
// kernel_launch
// ---------------------------------------------------------------------------
extern "C" void kernel_launch(void* const* d_in, const int* in_sizes, int n_in,
                              void* d_out, int out_size) {
    const float4* emb = (const float4*)d_in[0]; // [100000, 64] f32
    const float*  wv  = (const float*)d_in[1];  // [E] f32
    const int*    adj = (const int*)d_in[2];    // [2, E] int32

    int E = in_sizes[1];

    float4* x0; float4* x1;
    cudaGetSymbolAddress((void**)&x0, g_x0);
    cudaGetSymbolAddress((void**)&x1, g_x1);
    float4* out4 = reinterpret_cast<float4*>(d_out);

    const int T = 256;

    // 1) normalize + zero counters
    normalize_kernel<<<(N_NODES * 16 + T - 1) / T, T>>>(emb);
    // 2) in-degree histogram
    hist_kernel<<<(E + T - 1) / T, T>>>(adj, E);
    // 3) exclusive scan (two-level) + fixup
    scan_block_kernel<<<NUM_SB, SCAN_B>>>();
    scan_sums_kernel<<<1, 256>>>();
    scan_fixup_kernel<<<(N_NODES + T - 1) / T, T>>>(E);
    // 4) scatter into dst-sorted edge array
    scatter_kernel<<<(E + T - 1) / T, T>>>(adj, wv, E);
    // 5) layer 1: x1 = A x0
    pull_layer_kernel<<<(N_NODES * 32 + T - 1) / T, T>>>(x0, x1, nullptr, nullptr);
    // 6) layer 2 fused: out = x0 + x1 + A x1
    pull_layer_kernel<<<(N_NODES * 32 + T - 1) / T, T>>>(x1, out4, x0, x1);
}